// round 4
// baseline (speedup 1.0000x reference)
#include <cuda_runtime.h>

#define N_NODES 50000
#define E_EDGES 1600000
#define IN_F    256
#define AD      128
#define H_HEADS 8
// DK = 16, scale = 1/sqrt(16) = 0.25

// Scratch (device globals — no allocation allowed)
__device__ float g_q[N_NODES * AD];       // 25.6 MB
__device__ float g_k[N_NODES * AD];       // 25.6 MB
__device__ float g_s[N_NODES * H_HEADS];  // 1.6 MB softmax denominators

// ---------------------------------------------------------------------------
// Packed fp32x2 helpers (Blackwell FFMA2 path — only reachable via PTX)
// ---------------------------------------------------------------------------
__device__ __forceinline__ unsigned long long pack2(float lo, float hi) {
    unsigned long long r;
    asm("mov.b64 %0, {%1, %2};" : "=l"(r) : "f"(lo), "f"(hi));
    return r;
}
__device__ __forceinline__ float2 unpack2(unsigned long long v) {
    float2 f;
    asm("mov.b64 {%0, %1}, %2;" : "=f"(f.x), "=f"(f.y) : "l"(v));
    return f;
}
__device__ __forceinline__ void ffma2(unsigned long long& d,
                                      unsigned long long a,
                                      unsigned long long b) {
    asm("fma.rn.f32x2 %0, %1, %2, %0;" : "+l"(d) : "l"(a), "l"(b));
}

// ---------------------------------------------------------------------------
// Fused Q/K projection:  g_q/g_k[N,128] = hi @ W^T + b
// BM=64, BN=128 (full AD), BK=16, 256 threads, 4x8 per thread via FFMA2.
// grid = (782, 2): y=0 -> Q (also zeroes g_s), y=1 -> K.
// ---------------------------------------------------------------------------
#define BM 64
#define BN 128
#define BK 16
#define APAD 4    // As row stride 68 floats (272 B, 16B-aligned)
#define BPAD 4    // Bs row stride 132 floats (528 B, 16B-aligned)

__global__ __launch_bounds__(256) void gemm_qk_kernel(
    const float* __restrict__ hi,
    const float* __restrict__ Qw, const float* __restrict__ Qb,
    const float* __restrict__ Kw, const float* __restrict__ Kb)
{
    __shared__ float As[BK][BM + APAD];
    __shared__ float Bs[BK][BN + BPAD];

    const int tid = threadIdx.x;

    // Side job: y==0 blocks zero the softmax accumulator (2 floats/thread)
    if (blockIdx.y == 0) {
        const int z0 = blockIdx.x * 512 + tid * 2;
        if (z0 < N_NODES * H_HEADS)     g_s[z0] = 0.0f;
        if (z0 + 1 < N_NODES * H_HEADS) g_s[z0 + 1] = 0.0f;
    }

    const int tx = tid & 15;    // 0..15 -> 8 output cols each
    const int ty = tid >> 4;    // 0..15 -> 4 output rows each
    const int m0 = blockIdx.x * BM;
    const bool isK = (blockIdx.y != 0);
    const float* W    = isK ? Kw : Qw;
    const float* bias = isK ? Kb : Qb;
    float* outp       = isK ? g_k : g_q;

    // 4 rows x 4 col-pairs of packed accumulators (= 4x8 fp32)
    unsigned long long acc[4][4];
    {
        float4 b0 = *(const float4*)&bias[tx * 8];
        float4 b1 = *(const float4*)&bias[tx * 8 + 4];
        unsigned long long p0 = pack2(b0.x, b0.y);
        unsigned long long p1 = pack2(b0.z, b0.w);
        unsigned long long p2 = pack2(b1.x, b1.y);
        unsigned long long p3 = pack2(b1.z, b1.w);
        #pragma unroll
        for (int i = 0; i < 4; i++) {
            acc[i][0] = p0; acc[i][1] = p1; acc[i][2] = p2; acc[i][3] = p3;
        }
    }

    const int lrowA = tid >> 2;           // 0..63
    const int lc4A  = (tid & 3) * 4;      // 0,4,8,12

    for (int k0 = 0; k0 < IN_F; k0 += BK) {
        // A tile: 64x16, one float4 per thread, transposed into As[k][m]
        {
            float4 av = make_float4(0.f, 0.f, 0.f, 0.f);
            const int gm = m0 + lrowA;
            if (gm < N_NODES)
                av = *(const float4*)&hi[(size_t)gm * IN_F + k0 + lc4A];
            As[lc4A + 0][lrowA] = av.x;
            As[lc4A + 1][lrowA] = av.y;
            As[lc4A + 2][lrowA] = av.z;
            As[lc4A + 3][lrowA] = av.w;
        }
        // B tile: 128x16, two float4 per thread, transposed into Bs[k][n]
        #pragma unroll
        for (int t = 0; t < 2; t++) {
            const int lt = tid + t * 256;
            const int nrow = lt >> 2;            // 0..127
            const int c4   = (lt & 3) * 4;
            float4 bv = *(const float4*)&W[(size_t)nrow * IN_F + k0 + c4];
            Bs[c4 + 0][nrow] = bv.x;
            Bs[c4 + 1][nrow] = bv.y;
            Bs[c4 + 2][nrow] = bv.z;
            Bs[c4 + 3][nrow] = bv.w;
        }
        __syncthreads();

        #pragma unroll
        for (int k = 0; k < BK; k++) {
            float4 a4 = *(const float4*)&As[k][ty * 4];
            float4 b0 = *(const float4*)&Bs[k][tx * 8];
            float4 b1 = *(const float4*)&Bs[k][tx * 8 + 4];
            unsigned long long bb[4] = {
                pack2(b0.x, b0.y), pack2(b0.z, b0.w),
                pack2(b1.x, b1.y), pack2(b1.z, b1.w)
            };
            unsigned long long aa[4] = {
                pack2(a4.x, a4.x), pack2(a4.y, a4.y),
                pack2(a4.z, a4.z), pack2(a4.w, a4.w)
            };
            #pragma unroll
            for (int i = 0; i < 4; i++)
                #pragma unroll
                for (int j = 0; j < 4; j++)
                    ffma2(acc[i][j], aa[i], bb[j]);
        }
        __syncthreads();
    }

    #pragma unroll
    for (int i = 0; i < 4; i++) {
        const int gm = m0 + ty * 4 + i;
        if (gm < N_NODES) {
            float2 c0 = unpack2(acc[i][0]);
            float2 c1 = unpack2(acc[i][1]);
            float2 c2 = unpack2(acc[i][2]);
            float2 c3 = unpack2(acc[i][3]);
            float* row = &outp[(size_t)gm * AD + tx * 8];
            *(float4*)(row)     = make_float4(c0.x, c0.y, c1.x, c1.y);
            *(float4*)(row + 4) = make_float4(c2.x, c2.y, c3.x, c3.y);
        }
    }
}

// ---------------------------------------------------------------------------
// Edge kernel: one warp per edge.
//   lane i owns floats [4i, 4i+4) of the 128-dim vectors (head = i/4, DK=16).
//   prods[e,h] = dot(q[src]+radial*Qrw+Qrb, k[dst]) / 4
//   writes prods, writes exp(prods) into attention slot, atomicAdd to g_s.
// ---------------------------------------------------------------------------
__global__ __launch_bounds__(256) void edge_kernel(
    const int*   __restrict__ edge0,
    const int*   __restrict__ edge1,
    const float* __restrict__ radial,
    const float* __restrict__ Qrw,
    const float* __restrict__ Qrb,
    float* __restrict__ out_att,
    float* __restrict__ out_prods)
{
    const int warp = threadIdx.x >> 5;
    const int lane = threadIdx.x & 31;
    const int e = blockIdx.x * 8 + warp;
    if (e >= E_EDGES) return;

    // Per-lane radial projection constants (128 floats each, L1-resident)
    const float4 w4 = *(const float4*)&Qrw[lane * 4];
    const float4 b4 = *(const float4*)&Qrb[lane * 4];

    const int src = edge0[e];
    const int dst = edge1[e];
    const float r = radial[e];

    const float4 q4 = *(const float4*)&g_q[(size_t)src * AD + lane * 4];
    const float4 k4 = *(const float4*)&g_k[(size_t)dst * AD + lane * 4];

    const float sx = fmaf(r, w4.x, q4.x + b4.x);
    const float sy = fmaf(r, w4.y, q4.y + b4.y);
    const float sz = fmaf(r, w4.z, q4.z + b4.z);
    const float sw = fmaf(r, w4.w, q4.w + b4.w);

    float p = sx * k4.x + sy * k4.y + sz * k4.z + sw * k4.w;
    // reduce within each quad of lanes (one head = 4 lanes)
    p += __shfl_xor_sync(0xFFFFFFFFu, p, 1);
    p += __shfl_xor_sync(0xFFFFFFFFu, p, 2);
    p *= 0.25f;   // 1/sqrt(DK)

    // compact: lane h (0..7) grabs head value from lane 4h
    const float ph = __shfl_sync(0xFFFFFFFFu, p, (lane * 4) & 31);
    if (lane < H_HEADS) {
        out_prods[(size_t)e * H_HEADS + lane] = ph;
        const float ex = __expf(ph);
        out_att[(size_t)e * H_HEADS + lane] = ex;
        atomicAdd(&g_s[src * H_HEADS + lane], ex);
    }
}

// ---------------------------------------------------------------------------
// Reciprocal pass: g_s[i] = 1/g_s[i]  (only 400K full-accuracy divisions)
// ---------------------------------------------------------------------------
__global__ __launch_bounds__(256) void recip_kernel() {
    const int i = blockIdx.x * blockDim.x + threadIdx.x;
    if (i < N_NODES * H_HEADS) g_s[i] = 1.0f / g_s[i];
}

// ---------------------------------------------------------------------------
// Normalize: one thread per edge, float4 loads, multiply by reciprocal.
// ---------------------------------------------------------------------------
__global__ __launch_bounds__(256) void norm_kernel(
    const int* __restrict__ edge0,
    float* __restrict__ out_att)
{
    const int e = blockIdx.x * blockDim.x + threadIdx.x;
    if (e >= E_EDGES) return;
    const int src = edge0[e];
    const float4 r0 = *(const float4*)&g_s[src * H_HEADS];
    const float4 r1 = *(const float4*)&g_s[src * H_HEADS + 4];
    float4* a = (float4*)&out_att[(size_t)e * H_HEADS];
    float4 a0 = a[0];
    float4 a1 = a[1];
    a0.x *= r0.x; a0.y *= r0.y; a0.z *= r0.z; a0.w *= r0.w;
    a1.x *= r1.x; a1.y *= r1.y; a1.z *= r1.z; a1.w *= r1.w;
    a[0] = a0;
    a[1] = a1;
}

// ---------------------------------------------------------------------------
// Launch
// Inputs (metadata order): hi, radial, Qw, Qb, Qrw, Qrb, Kw, Kb, edge
// Output: [attention (E*H) | prods (E*H)] fp32
// ---------------------------------------------------------------------------
extern "C" void kernel_launch(void* const* d_in, const int* in_sizes, int n_in,
                              void* d_out, int out_size)
{
    const float* hi     = (const float*)d_in[0];
    const float* radial = (const float*)d_in[1];
    const float* Qw     = (const float*)d_in[2];
    const float* Qb     = (const float*)d_in[3];
    const float* Qrw    = (const float*)d_in[4];
    const float* Qrb    = (const float*)d_in[5];
    const float* Kw     = (const float*)d_in[6];
    const float* Kb     = (const float*)d_in[7];
    const int*   edge   = (const int*)d_in[8];
    const int*   edge0  = edge;
    const int*   edge1  = edge + E_EDGES;

    float* out_att   = (float*)d_out;
    float* out_prods = out_att + (size_t)E_EDGES * H_HEADS;

    // 1. Q/K projections (+ zero softmax accumulator as a side job)
    dim3 ggrid((N_NODES + BM - 1) / BM, 2);   // 782 x 2
    gemm_qk_kernel<<<ggrid, 256>>>(hi, Qw, Qb, Kw, Kb);

    // 2. per-edge dot + exp + segment sums (1 warp / edge, 8 warps / block)
    edge_kernel<<<(E_EDGES + 7) / 8, 256>>>(edge0, edge1, radial, Qrw, Qrb,
                                            out_att, out_prods);

    // 3. reciprocal of denominators
    recip_kernel<<<(N_NODES * H_HEADS + 255) / 256, 256>>>();

    // 4. normalize
    norm_kernel<<<(E_EDGES + 255) / 256, 256>>>(edge0, out_att);
}

// round 17
// speedup vs baseline: 1.4996x; 1.4996x over previous
#include <cuda_runtime.h>

#define N_NODES 50000
#define E_EDGES 1600000
#define IN_F    256
#define AD      128
#define H_HEADS 8
// DK = 16, scale = 0.25

// Scratch (device globals — no allocation allowed)
__device__ float g_q[N_NODES * AD];       // 25.6 MB
__device__ float g_k[N_NODES * AD];       // 25.6 MB
__device__ float g_s[N_NODES * H_HEADS];  // 1.6 MB softmax denominators

// ---------------------------------------------------------------------------
// bf16 split helpers:  x = hi + lo,  hi = bf16_rn(x), lo = bf16_rn(x - hi)
// (x - hi is exact in fp32; dropped lo*lo term ~2^-16 relative)
// cvt.rn.bf16x2.f32 d, a, b  ->  d = { lo16 = cvt(b), hi16 = cvt(a) }
// ---------------------------------------------------------------------------
__device__ __forceinline__ void split2(float x, float y,
                                       unsigned& h2, unsigned& l2) {
    unsigned h;
    asm("cvt.rn.bf16x2.f32 %0, %1, %2;" : "=r"(h) : "f"(y), "f"(x));
    float hx = __uint_as_float(h << 16);
    float hy = __uint_as_float(h & 0xFFFF0000u);
    float lx = x - hx;
    float ly = y - hy;
    asm("cvt.rn.bf16x2.f32 %0, %1, %2;" : "=r"(l2) : "f"(ly), "f"(lx));
    h2 = h;
}

__device__ __forceinline__ void mma16816(float* d,
                                         unsigned a0, unsigned a1,
                                         unsigned a2, unsigned a3,
                                         unsigned b0, unsigned b1) {
    asm volatile(
        "mma.sync.aligned.m16n8k16.row.col.f32.bf16.bf16.f32 "
        "{%0,%1,%2,%3}, {%4,%5,%6,%7}, {%8,%9}, {%0,%1,%2,%3};"
        : "+f"(d[0]), "+f"(d[1]), "+f"(d[2]), "+f"(d[3])
        : "r"(a0), "r"(a1), "r"(a2), "r"(a3), "r"(b0), "r"(b1));
}

// ---------------------------------------------------------------------------
// Tensor-core Q/K projection:  g_q/g_k[N,128] = hi @ W^T + b
// BM=128, BN=64, BK=32. 256 threads = 8 warps (2 m-halves x 4 n-chunks).
// Warp tile 64m x 16n = 4x2 mma tiles. bf16 hi/lo 3-pass for fp32 accuracy.
// grid = (391, 4): y in {0,1} -> Q cols [0,64),[64,128); {2,3} -> K.
// ---------------------------------------------------------------------------
#define BM 128
#define BN 64
#define BK 32
#define KST 40   // smem row stride in bf16 elems: 20 banks -> conflict-free

__global__ __launch_bounds__(256) void gemm_qk_mma(
    const float* __restrict__ hi,
    const float* __restrict__ Qw, const float* __restrict__ Qb,
    const float* __restrict__ Kw, const float* __restrict__ Kb)
{
    __shared__ __align__(16) unsigned short sAhi[BM * KST];
    __shared__ __align__(16) unsigned short sAlo[BM * KST];
    __shared__ __align__(16) unsigned short sWhi[BN * KST];
    __shared__ __align__(16) unsigned short sWlo[BN * KST];

    const int tid  = threadIdx.x;
    const int lane = tid & 31;
    const int warp = tid >> 5;
    const int wm   = warp & 1;        // m-half: 0,1
    const int wn   = warp >> 1;       // n-chunk: 0..3
    const int m0   = blockIdx.x * BM;
    const int by   = blockIdx.y;
    const bool isK = (by >= 2);
    const float* W    = isK ? Kw : Qw;
    const float* bias = isK ? Kb : Qb;
    const int nblk    = (by & 1) * 64;    // col offset within the 128
    float* outp       = isK ? g_k : g_q;

    // Side job: by==0 blocks zero g_s (391*256*4 = 400384 >= 400000)
    if (by == 0) {
        int z = (blockIdx.x * 256 + tid) * 4;
        #pragma unroll
        for (int i = 0; i < 4; i++)
            if (z + i < N_NODES * H_HEADS) g_s[z + i] = 0.0f;
    }

    float acc[4][2][4];   // [m-tile][n-tile][c0..c3]
    #pragma unroll
    for (int a = 0; a < 4; a++)
        #pragma unroll
        for (int b = 0; b < 2; b++)
            #pragma unroll
            for (int c = 0; c < 4; c++) acc[a][b][c] = 0.0f;

    const int gid = lane >> 2;        // 0..7
    const int tig = lane & 3;         // 0..3

    for (int k0 = 0; k0 < IN_F; k0 += BK) {
        // ---- stage A: 128 rows x 32 k (fp32 -> bf16 hi/lo) ----
        #pragma unroll
        for (int s = 0; s < 4; s++) {
            int slot = tid + s * 256;          // 0..1023
            int row  = slot >> 3;              // 0..127
            int kc   = (slot & 7) * 4;         // 0,4,...,28
            int gm   = m0 + row;
            float4 v = make_float4(0.f, 0.f, 0.f, 0.f);
            if (gm < N_NODES)
                v = *(const float4*)&hi[(size_t)gm * IN_F + k0 + kc];
            unsigned h01, l01, h23, l23;
            split2(v.x, v.y, h01, l01);
            split2(v.z, v.w, h23, l23);
            *(unsigned*)&sAhi[row * KST + kc]     = h01;
            *(unsigned*)&sAhi[row * KST + kc + 2] = h23;
            *(unsigned*)&sAlo[row * KST + kc]     = l01;
            *(unsigned*)&sAlo[row * KST + kc + 2] = l23;
        }
        // ---- stage W: 64 rows x 32 k ----
        #pragma unroll
        for (int s = 0; s < 2; s++) {
            int slot = tid + s * 256;          // 0..511
            int row  = slot >> 3;              // 0..63
            int kc   = (slot & 7) * 4;
            float4 v = *(const float4*)&W[(size_t)(nblk + row) * IN_F + k0 + kc];
            unsigned h01, l01, h23, l23;
            split2(v.x, v.y, h01, l01);
            split2(v.z, v.w, h23, l23);
            *(unsigned*)&sWhi[row * KST + kc]     = h01;
            *(unsigned*)&sWhi[row * KST + kc + 2] = h23;
            *(unsigned*)&sWlo[row * KST + kc]     = l01;
            *(unsigned*)&sWlo[row * KST + kc + 2] = l23;
        }
        __syncthreads();

        // ---- compute: two k16 steps ----
        #pragma unroll
        for (int kk = 0; kk < BK; kk += 16) {
            // B fragments for this warp's 2 n-tiles (hi & lo)
            unsigned bh[2][2], bl[2][2];
            #pragma unroll
            for (int nt = 0; nt < 2; nt++) {
                int ns = wn * 16 + nt * 8 + gid;          // 0..63
                int kb = kk + tig * 2;
                bh[nt][0] = *(const unsigned*)&sWhi[ns * KST + kb];
                bh[nt][1] = *(const unsigned*)&sWhi[ns * KST + kb + 8];
                bl[nt][0] = *(const unsigned*)&sWlo[ns * KST + kb];
                bl[nt][1] = *(const unsigned*)&sWlo[ns * KST + kb + 8];
            }
            #pragma unroll
            for (int mt = 0; mt < 4; mt++) {
                int r  = wm * 64 + mt * 16 + gid;         // 0..127
                int ka = kk + tig * 2;
                unsigned ah0 = *(const unsigned*)&sAhi[r * KST + ka];
                unsigned ah1 = *(const unsigned*)&sAhi[(r + 8) * KST + ka];
                unsigned ah2 = *(const unsigned*)&sAhi[r * KST + ka + 8];
                unsigned ah3 = *(const unsigned*)&sAhi[(r + 8) * KST + ka + 8];
                unsigned al0 = *(const unsigned*)&sAlo[r * KST + ka];
                unsigned al1 = *(const unsigned*)&sAlo[(r + 8) * KST + ka];
                unsigned al2 = *(const unsigned*)&sAlo[r * KST + ka + 8];
                unsigned al3 = *(const unsigned*)&sAlo[(r + 8) * KST + ka + 8];
                #pragma unroll
                for (int nt = 0; nt < 2; nt++) {
                    mma16816(acc[mt][nt], ah0, ah1, ah2, ah3, bh[nt][0], bh[nt][1]);
                    mma16816(acc[mt][nt], ah0, ah1, ah2, ah3, bl[nt][0], bl[nt][1]);
                    mma16816(acc[mt][nt], al0, al1, al2, al3, bh[nt][0], bh[nt][1]);
                }
            }
        }
        __syncthreads();
    }

    // ---- epilogue: bias + store ----
    #pragma unroll
    for (int nt = 0; nt < 2; nt++) {
        const int col = nblk + wn * 16 + nt * 8 + tig * 2;   // 0..127
        const float b0 = bias[col];
        const float b1 = bias[col + 1];
        #pragma unroll
        for (int mt = 0; mt < 4; mt++) {
            const int r0 = m0 + wm * 64 + mt * 16 + gid;
            if (r0 < N_NODES) {
                float2 v = make_float2(acc[mt][nt][0] + b0, acc[mt][nt][1] + b1);
                *(float2*)&outp[(size_t)r0 * AD + col] = v;
            }
            const int r1 = r0 + 8;
            if (r1 < N_NODES) {
                float2 v = make_float2(acc[mt][nt][2] + b0, acc[mt][nt][3] + b1);
                *(float2*)&outp[(size_t)r1 * AD + col] = v;
            }
        }
    }
}

// ---------------------------------------------------------------------------
// Edge kernel: one warp per edge. lane i owns floats [4i,4i+4) (head = i/4).
// prods[e,h] = dot(q[src]+radial*Qrw+Qrb, k[dst]) / 4
// writes prods, exp(prods) into attention slot, atomicAdd exp to g_s[src,h].
// ---------------------------------------------------------------------------
__global__ __launch_bounds__(256) void edge_kernel(
    const int*   __restrict__ edge0,
    const int*   __restrict__ edge1,
    const float* __restrict__ radial,
    const float* __restrict__ Qrw,
    const float* __restrict__ Qrb,
    float* __restrict__ out_att,
    float* __restrict__ out_prods)
{
    const int warp = threadIdx.x >> 5;
    const int lane = threadIdx.x & 31;
    const int e = blockIdx.x * 8 + warp;
    if (e >= E_EDGES) return;

    const float4 w4 = *(const float4*)&Qrw[lane * 4];
    const float4 b4 = *(const float4*)&Qrb[lane * 4];

    const int src = edge0[e];
    const int dst = edge1[e];
    const float r = radial[e];

    const float4 q4 = *(const float4*)&g_q[(size_t)src * AD + lane * 4];
    const float4 k4 = *(const float4*)&g_k[(size_t)dst * AD + lane * 4];

    const float sx = fmaf(r, w4.x, q4.x + b4.x);
    const float sy = fmaf(r, w4.y, q4.y + b4.y);
    const float sz = fmaf(r, w4.z, q4.z + b4.z);
    const float sw = fmaf(r, w4.w, q4.w + b4.w);

    float p = sx * k4.x + sy * k4.y + sz * k4.z + sw * k4.w;
    p += __shfl_xor_sync(0xFFFFFFFFu, p, 1);
    p += __shfl_xor_sync(0xFFFFFFFFu, p, 2);
    p *= 0.25f;   // 1/sqrt(DK)

    const float ph = __shfl_sync(0xFFFFFFFFu, p, (lane * 4) & 31);
    if (lane < H_HEADS) {
        out_prods[(size_t)e * H_HEADS + lane] = ph;
        const float ex = __expf(ph);
        out_att[(size_t)e * H_HEADS + lane] = ex;
        atomicAdd(&g_s[src * H_HEADS + lane], ex);
    }
}

// ---------------------------------------------------------------------------
// Reciprocal pass: g_s[i] = 1/g_s[i]  (400K full-accuracy divisions)
// ---------------------------------------------------------------------------
__global__ __launch_bounds__(256) void recip_kernel() {
    const int i = blockIdx.x * blockDim.x + threadIdx.x;
    if (i < N_NODES * H_HEADS) g_s[i] = 1.0f / g_s[i];
}

// ---------------------------------------------------------------------------
// Normalize: one thread per edge, float4, multiply by reciprocal.
// ---------------------------------------------------------------------------
__global__ __launch_bounds__(256) void norm_kernel(
    const int* __restrict__ edge0,
    float* __restrict__ out_att)
{
    const int e = blockIdx.x * blockDim.x + threadIdx.x;
    if (e >= E_EDGES) return;
    const int src = edge0[e];
    const float4 r0 = *(const float4*)&g_s[src * H_HEADS];
    const float4 r1 = *(const float4*)&g_s[src * H_HEADS + 4];
    float4* a = (float4*)&out_att[(size_t)e * H_HEADS];
    float4 a0 = a[0];
    float4 a1 = a[1];
    a0.x *= r0.x; a0.y *= r0.y; a0.z *= r0.z; a0.w *= r0.w;
    a1.x *= r1.x; a1.y *= r1.y; a1.z *= r1.z; a1.w *= r1.w;
    a[0] = a0;
    a[1] = a1;
}

// ---------------------------------------------------------------------------
// Launch
// Inputs (metadata order): hi, radial, Qw, Qb, Qrw, Qrb, Kw, Kb, edge
// Output: [attention (E*H) | prods (E*H)] fp32
// ---------------------------------------------------------------------------
extern "C" void kernel_launch(void* const* d_in, const int* in_sizes, int n_in,
                              void* d_out, int out_size)
{
    const float* hi     = (const float*)d_in[0];
    const float* radial = (const float*)d_in[1];
    const float* Qw     = (const float*)d_in[2];
    const float* Qb     = (const float*)d_in[3];
    const float* Qrw    = (const float*)d_in[4];
    const float* Qrb    = (const float*)d_in[5];
    const float* Kw     = (const float*)d_in[6];
    const float* Kb     = (const float*)d_in[7];
    const int*   edge   = (const int*)d_in[8];
    const int*   edge0  = edge;
    const int*   edge1  = edge + E_EDGES;

    float* out_att   = (float*)d_out;
    float* out_prods = out_att + (size_t)E_EDGES * H_HEADS;

    // 1. Q/K projections on tensor cores (+ zero g_s side job)
    dim3 ggrid((N_NODES + BM - 1) / BM, 4);   // 391 x 4
    gemm_qk_mma<<<ggrid, 256>>>(hi, Qw, Qb, Kw, Kb);

    // 2. per-edge dot + exp + segment sums
    edge_kernel<<<(E_EDGES + 7) / 8, 256>>>(edge0, edge1, radial, Qrw, Qrb,
                                            out_att, out_prods);

    // 3. reciprocal of denominators
    recip_kernel<<<(N_NODES * H_HEADS + 255) / 256, 256>>>();

    // 4. normalize
    norm_kernel<<<(E_EDGES + 255) / 256, 256>>>(edge0, out_att);
}